// round 3
// baseline (speedup 1.0000x reference)
#include <cuda_runtime.h>

// ---------------- problem constants ----------------
constexpr int B_  = 4;
constexpr int T_  = 4096;
constexpr int C_  = 1024;
constexpr int NH_ = 16;
constexpr int HD_ = 64;
constexpr int A_  = 64;
constexpr int C3_ = 3 * C_;          // 3072
constexpr int BT_ = B_ * T_;         // 16384 rows
constexpr int BH_ = B_ * NH_;        // 64 (b,h) pairs
constexpr int NCHUNK_ = 8;           // T split for stage-1
constexpr int CT_ = T_ / NCHUNK_;    // 512 keys per chunk
constexpr int KT_ = 64;              // key tile
constexpr float SCALE_ = 0.125f;     // 1/sqrt(64)

// ---------------- scratch (device globals: no cudaMalloc allowed) ----------------
__device__ float g_qkv[(size_t)BT_ * C3_];                    // [B*T, 3C]
__device__ float g_qa[NH_ * A_ * HD_];                        // q_a (batch-independent)
__device__ float g_pm[BH_ * NCHUNK_ * A_];                    // stage-1 partial max
__device__ float g_pl[BH_ * NCHUNK_ * A_];                    // stage-1 partial sum
__device__ float g_pacc[(size_t)BH_ * NCHUNK_ * A_ * HD_];    // stage-1 partial acc
__device__ float g_c1[BH_ * A_ * HD_];                        // agent context
__device__ float g_c2[(size_t)BT_ * C_];                      // token context [B*T, C]
__device__ float g_wcomb[C_ * C_];                            // Wproj @ Wout
__device__ float g_bcomb[C_];                                 // Wproj @ bout + bproj

// =====================================================================
// Generic tiled GEMM:  C[M,N] = A[M,K] @ op(B) + bias
//   BTR=1 : B is [N,K] row-major (C = A @ B^T)   -- weight layout
//   BTR=0 : B is [K,N] row-major (C = A @ B)
// BM=BN=128, BK=16, 256 threads, 8x8 strided fragments.
// All shapes used are multiples of the tiles (no bounds checks).
// =====================================================================
template<int BTR>
__global__ __launch_bounds__(256)
void gemm_bias_kernel(const float* __restrict__ A, const float* __restrict__ Bm,
                      const float* __restrict__ bias, float* __restrict__ Cm,
                      int M, int N, int K)
{
    __shared__ float As[16][132];
    __shared__ float Bs[16][132];
    const int tid = threadIdx.x;
    const int tx = tid & 15, ty = tid >> 4;
    const int m0 = blockIdx.y * 128, n0 = blockIdx.x * 128;

    float acc[8][8];
#pragma unroll
    for (int r = 0; r < 8; r++)
#pragma unroll
        for (int c = 0; c < 8; c++) acc[r][c] = 0.f;

    for (int k0 = 0; k0 < K; k0 += 16) {
#pragma unroll
        for (int q = 0; q < 2; q++) {                 // A tile: 128 rows x 16 k
            int lin = tid + q * 256;
            int row = lin >> 2, c4 = lin & 3;
            const float4 v = *reinterpret_cast<const float4*>(
                A + (size_t)(m0 + row) * K + k0 + c4 * 4);
            As[c4*4+0][row] = v.x; As[c4*4+1][row] = v.y;
            As[c4*4+2][row] = v.z; As[c4*4+3][row] = v.w;
        }
        if (BTR) {
#pragma unroll
            for (int q = 0; q < 2; q++) {             // B tile: 128 n-rows x 16 k
                int lin = tid + q * 256;
                int row = lin >> 2, c4 = lin & 3;
                const float4 v = *reinterpret_cast<const float4*>(
                    Bm + (size_t)(n0 + row) * K + k0 + c4 * 4);
                Bs[c4*4+0][row] = v.x; Bs[c4*4+1][row] = v.y;
                Bs[c4*4+2][row] = v.z; Bs[c4*4+3][row] = v.w;
            }
        } else {
#pragma unroll
            for (int q = 0; q < 2; q++) {             // B tile: 16 k-rows x 128 n
                int lin = tid + q * 256;
                int row = lin >> 5, c4 = lin & 31;
                const float4 v = *reinterpret_cast<const float4*>(
                    Bm + (size_t)(k0 + row) * N + n0 + c4 * 4);
                Bs[row][c4*4+0] = v.x; Bs[row][c4*4+1] = v.y;
                Bs[row][c4*4+2] = v.z; Bs[row][c4*4+3] = v.w;
            }
        }
        __syncthreads();
#pragma unroll
        for (int kk = 0; kk < 16; kk++) {
            float af[8], bf[8];
#pragma unroll
            for (int r = 0; r < 8; r++) af[r] = As[kk][ty + 16*r];
#pragma unroll
            for (int c = 0; c < 8; c++) bf[c] = Bs[kk][tx + 16*c];
#pragma unroll
            for (int r = 0; r < 8; r++)
#pragma unroll
                for (int c = 0; c < 8; c++) acc[r][c] = fmaf(af[r], bf[c], acc[r][c]);
        }
        __syncthreads();
    }

    float bb[8];
#pragma unroll
    for (int c = 0; c < 8; c++) bb[c] = bias ? bias[n0 + tx + 16*c] : 0.f;
#pragma unroll
    for (int r = 0; r < 8; r++) {
        const int m = m0 + ty + 16*r;
#pragma unroll
        for (int c = 0; c < 8; c++) {
            const int n = n0 + tx + 16*c;
            Cm[(size_t)m * N + n] = acc[r][c] + bb[c];
        }
    }
}

// =====================================================================
// q_a[h] = agent_tokens[h] @ Wq^T + bq   (batch-independent)
// one block per head, 64x64x64, 4x4 strided fragments
// =====================================================================
__global__ __launch_bounds__(256)
void qa_kernel(const float* __restrict__ ag, const float* __restrict__ Wq,
               const float* __restrict__ bq, float* __restrict__ qa)
{
    __shared__ float sA[64 * 65];
    __shared__ float sW[64 * 65];
    const int tid = threadIdx.x;
    const int tx = tid & 15, ty = tid >> 4;
    const int h = blockIdx.x;

    for (int idx = tid; idx < 4096; idx += 256) {
        sA[(idx >> 6) * 65 + (idx & 63)] = ag[h * 4096 + idx];
        sW[(idx >> 6) * 65 + (idx & 63)] = Wq[idx];
    }
    __syncthreads();

    float acc[4][4];
#pragma unroll
    for (int r = 0; r < 4; r++)
#pragma unroll
        for (int c = 0; c < 4; c++) acc[r][c] = bq[tx + 16*c];
#pragma unroll 8
    for (int e = 0; e < 64; e++) {
        float af[4], wf[4];
#pragma unroll
        for (int r = 0; r < 4; r++) af[r] = sA[(ty + 16*r) * 65 + e];
#pragma unroll
        for (int c = 0; c < 4; c++) wf[c] = sW[(tx + 16*c) * 65 + e];
#pragma unroll
        for (int r = 0; r < 4; r++)
#pragma unroll
            for (int c = 0; c < 4; c++) acc[r][c] = fmaf(af[r], wf[c], acc[r][c]);
    }
#pragma unroll
    for (int r = 0; r < 4; r++)
#pragma unroll
        for (int c = 0; c < 4; c++)
            qa[h * 4096 + (ty + 16*r) * 64 + tx + 16*c] = acc[r][c];
}

// b' = Wproj @ bout + bproj
__global__ void bcomb_kernel(const float* __restrict__ Wproj, const float* __restrict__ bout,
                             const float* __restrict__ bproj, float* __restrict__ bcomb)
{
    const int i = blockIdx.x * 256 + threadIdx.x;
    float s = bproj[i];
    for (int k = 0; k < C_; k++) s = fmaf(Wproj[(size_t)i * C_ + k], bout[k], s);
    bcomb[i] = s;
}

// =====================================================================
// Stage 1 (fused): per (b,h,chunk) block.
//   streams 64-key tiles: k -> k_a = k@Wk^T+bk, score vs q_a, online
//   softmax, v -> v_a = v@Wv^T+bv, acc += P @ v_a.
// Emits split-T partials (m, l, acc) for a tiny combine kernel.
// =====================================================================
constexpr int S1P = 65;
constexpr int S1_SMEM = 6 * 64 * S1P * (int)sizeof(float);   // 99840 B (dynamic)

__global__ __launch_bounds__(256)
void stage1_kernel(const float* __restrict__ qkv, const float* __restrict__ qa,
                   const float* __restrict__ Wk, const float* __restrict__ bk,
                   const float* __restrict__ Wv, const float* __restrict__ bv,
                   float* __restrict__ pm, float* __restrict__ pl,
                   float* __restrict__ pacc)
{
    extern __shared__ float sm1[];
    float* sQa = sm1;                 // [64][65]  q_a (a,d)
    float* sWk = sQa + 64 * S1P;      // [64][65]  Wk (d,e)
    float* sWv = sWk + 64 * S1P;      // [64][65]  Wv (d,e)
    float* sX  = sWv + 64 * S1P;      // [64][65]  raw k/v tile (t,e)
    float* sY  = sX  + 64 * S1P;      // [64][65]  k_a / v_a tile (t,d)
    float* sP  = sY  + 64 * S1P;      // [64][65]  exp scores (a,t)

    const int tid = threadIdx.x;
    const int tx = tid & 15, ty = tid >> 4;
    const int chunk = blockIdx.x, bh = blockIdx.y;
    const int b = bh >> 4, h = bh & 15;

    for (int idx = tid; idx < 4096; idx += 256) {
        const int r = idx >> 6, cc = idx & 63;
        sQa[r * S1P + cc] = qa[h * 4096 + idx];
        sWk[r * S1P + cc] = Wk[idx];
        sWv[r * S1P + cc] = Wv[idx];
    }
    float bkr[4], bvr[4];
#pragma unroll
    for (int c = 0; c < 4; c++) { bkr[c] = bk[tx + 16*c]; bvr[c] = bv[tx + 16*c]; }

    float m_run[4], l_run[4], acc[4][4];
#pragma unroll
    for (int r = 0; r < 4; r++) {
        m_run[r] = -1e30f; l_run[r] = 0.f;
#pragma unroll
        for (int c = 0; c < 4; c++) acc[r][c] = 0.f;
    }

    const size_t rowbase = (size_t)(b * T_) * C3_;

    for (int kt = 0; kt < CT_ / KT_; kt++) {
        const int t0 = chunk * CT_ + kt * KT_;

        // load raw K tile -> sX
        for (int idx = tid; idx < 1024; idx += 256) {
            const int row = idx >> 4, c4 = idx & 15;
            const float4 v = *reinterpret_cast<const float4*>(
                qkv + rowbase + (size_t)(t0 + row) * C3_ + C_ + h * 64 + c4 * 4);
            float* d = &sX[row * S1P + c4 * 4];
            d[0] = v.x; d[1] = v.y; d[2] = v.z; d[3] = v.w;
        }
        __syncthreads();   // (a) K loaded; prev-iter PV reads of sY/sP done

        // k_a = K @ Wk^T + bk  -> sY
        {
            float ka[4][4];
#pragma unroll
            for (int r = 0; r < 4; r++)
#pragma unroll
                for (int c = 0; c < 4; c++) ka[r][c] = bkr[c];
#pragma unroll 8
            for (int e = 0; e < 64; e++) {
                float xa[4], wb[4];
#pragma unroll
                for (int r = 0; r < 4; r++) xa[r] = sX[(ty + 16*r) * S1P + e];
#pragma unroll
                for (int c = 0; c < 4; c++) wb[c] = sWk[(tx + 16*c) * S1P + e];
#pragma unroll
                for (int r = 0; r < 4; r++)
#pragma unroll
                    for (int c = 0; c < 4; c++) ka[r][c] = fmaf(xa[r], wb[c], ka[r][c]);
            }
#pragma unroll
            for (int r = 0; r < 4; r++)
#pragma unroll
                for (int c = 0; c < 4; c++)
                    sY[(ty + 16*r) * S1P + tx + 16*c] = ka[r][c];
        }
        __syncthreads();   // (b) sY(k_a) ready, sX free

        // load raw V tile -> sX (overlaps with score compute below)
        for (int idx = tid; idx < 1024; idx += 256) {
            const int row = idx >> 4, c4 = idx & 15;
            const float4 v = *reinterpret_cast<const float4*>(
                qkv + rowbase + (size_t)(t0 + row) * C3_ + 2 * C_ + h * 64 + c4 * 4);
            float* d = &sX[row * S1P + c4 * 4];
            d[0] = v.x; d[1] = v.y; d[2] = v.z; d[3] = v.w;
        }

        // S = q_a @ k_a^T * scale, online softmax, P -> sP
        {
            float s[4][4];
#pragma unroll
            for (int r = 0; r < 4; r++)
#pragma unroll
                for (int c = 0; c < 4; c++) s[r][c] = 0.f;
#pragma unroll 8
            for (int e = 0; e < 64; e++) {
                float qf[4], kf[4];
#pragma unroll
                for (int r = 0; r < 4; r++) qf[r] = sQa[(ty + 16*r) * S1P + e];
#pragma unroll
                for (int c = 0; c < 4; c++) kf[c] = sY[(tx + 16*c) * S1P + e];
#pragma unroll
                for (int r = 0; r < 4; r++)
#pragma unroll
                    for (int c = 0; c < 4; c++) s[r][c] = fmaf(qf[r], kf[c], s[r][c]);
            }
#pragma unroll
            for (int r = 0; r < 4; r++) {
                float mt = -1e30f;
#pragma unroll
                for (int c = 0; c < 4; c++) { s[r][c] *= SCALE_; mt = fmaxf(mt, s[r][c]); }
#pragma unroll
                for (int ms = 8; ms >= 1; ms >>= 1)
                    mt = fmaxf(mt, __shfl_xor_sync(0xffffffffu, mt, ms));
                const float mn = fmaxf(m_run[r], mt);
                const float corr = __expf(m_run[r] - mn);
                float rs = 0.f;
#pragma unroll
                for (int c = 0; c < 4; c++) {
                    const float p = __expf(s[r][c] - mn);
                    sP[(ty + 16*r) * S1P + tx + 16*c] = p;
                    rs += p;
                }
#pragma unroll
                for (int ms = 8; ms >= 1; ms >>= 1)
                    rs += __shfl_xor_sync(0xffffffffu, rs, ms);
                l_run[r] = l_run[r] * corr + rs;
                m_run[r] = mn;
#pragma unroll
                for (int c = 0; c < 4; c++) acc[r][c] *= corr;
            }
        }
        __syncthreads();   // (c) sX(V) + sP ready; score reads of sY done

        // v_a = V @ Wv^T + bv -> sY
        {
            float va[4][4];
#pragma unroll
            for (int r = 0; r < 4; r++)
#pragma unroll
                for (int c = 0; c < 4; c++) va[r][c] = bvr[c];
#pragma unroll 8
            for (int e = 0; e < 64; e++) {
                float xa[4], wb[4];
#pragma unroll
                for (int r = 0; r < 4; r++) xa[r] = sX[(ty + 16*r) * S1P + e];
#pragma unroll
                for (int c = 0; c < 4; c++) wb[c] = sWv[(tx + 16*c) * S1P + e];
#pragma unroll
                for (int r = 0; r < 4; r++)
#pragma unroll
                    for (int c = 0; c < 4; c++) va[r][c] = fmaf(xa[r], wb[c], va[r][c]);
            }
#pragma unroll
            for (int r = 0; r < 4; r++)
#pragma unroll
                for (int c = 0; c < 4; c++)
                    sY[(ty + 16*r) * S1P + tx + 16*c] = va[r][c];
        }
        __syncthreads();   // (d) sY(v_a) ready

        // acc += P @ v_a
#pragma unroll 8
        for (int t = 0; t < 64; t++) {
            float pf[4], vf[4];
#pragma unroll
            for (int r = 0; r < 4; r++) pf[r] = sP[(ty + 16*r) * S1P + t];
#pragma unroll
            for (int c = 0; c < 4; c++) vf[c] = sY[t * S1P + tx + 16*c];
#pragma unroll
            for (int r = 0; r < 4; r++)
#pragma unroll
                for (int c = 0; c < 4; c++) acc[r][c] = fmaf(pf[r], vf[c], acc[r][c]);
        }
    }

    const int pi = bh * NCHUNK_ + chunk;
    if (tx == 0) {
#pragma unroll
        for (int r = 0; r < 4; r++) {
            pm[pi * 64 + ty + 16*r] = m_run[r];
            pl[pi * 64 + ty + 16*r] = l_run[r];
        }
    }
#pragma unroll
    for (int r = 0; r < 4; r++)
#pragma unroll
        for (int c = 0; c < 4; c++)
            pacc[(size_t)pi * 4096 + (ty + 16*r) * 64 + tx + 16*c] = acc[r][c];
}

// combine split-T partials -> c1[b,h,a,d]
__global__ __launch_bounds__(256)
void s1combine_kernel(const float* __restrict__ pm, const float* __restrict__ pl,
                      const float* __restrict__ pacc, float* __restrict__ c1)
{
    const int bh = blockIdx.x;
    const int tid = threadIdx.x;
    const int a = tid >> 2, dg = tid & 3;

    float mc[NCHUNK_], lc[NCHUNK_];
    float m = -1e30f;
#pragma unroll
    for (int c = 0; c < NCHUNK_; c++) {
        mc[c] = pm[(bh * NCHUNK_ + c) * 64 + a];
        lc[c] = pl[(bh * NCHUNK_ + c) * 64 + a];
        m = fmaxf(m, mc[c]);
    }
    float l = 0.f, w[NCHUNK_];
#pragma unroll
    for (int c = 0; c < NCHUNK_; c++) { w[c] = __expf(mc[c] - m); l += lc[c] * w[c]; }
    const float inv = 1.f / l;
#pragma unroll
    for (int j = 0; j < 16; j++) {
        const int d = dg * 16 + j;
        float s = 0.f;
#pragma unroll
        for (int c = 0; c < NCHUNK_; c++)
            s += pacc[(size_t)(bh * NCHUNK_ + c) * 4096 + a * 64 + d] * w[c];
        c1[bh * 4096 + a * 64 + d] = s * inv;
    }
}

// =====================================================================
// Stage 2: per (b,h, 128-token tile). A=64 keys -> exact softmax.
// Emits s2 (output #2) and c2 (input of final GEMM) directly.
// =====================================================================
constexpr int S2P = 65;
constexpr int S2_SMEM = (64 + 128 + 128) * S2P * (int)sizeof(float);  // 83200 B

__global__ __launch_bounds__(256)
void stage2_kernel(const float* __restrict__ qkv, const float* __restrict__ c1,
                   float* __restrict__ s2out, float* __restrict__ c2)
{
    extern __shared__ float sm2[];
    float* sC1 = sm2;                  // [64][65]  c1 (a,d)
    float* sQ  = sC1 + 64 * S2P;       // [128][65] q (t,d)
    float* sP  = sQ + 128 * S2P;       // [128][65] softmax (t,a)

    const int tid = threadIdx.x;
    const int tx = tid & 15, ty = tid >> 4;
    const int bh = blockIdx.y;
    const int b = bh >> 4, h = bh & 15;
    const int t0 = blockIdx.x * 128;

    for (int idx = tid; idx < 4096; idx += 256)
        sC1[(idx >> 6) * S2P + (idx & 63)] = c1[bh * 4096 + idx];
    for (int idx = tid; idx < 2048; idx += 256) {
        const int row = idx >> 4, c4 = idx & 15;
        const float4 v = *reinterpret_cast<const float4*>(
            qkv + (size_t)(b * T_ + t0 + row) * C3_ + h * 64 + c4 * 4);
        float* d = &sQ[row * S2P + c4 * 4];
        d[0] = v.x; d[1] = v.y; d[2] = v.z; d[3] = v.w;
    }
    __syncthreads();

    // S = q @ c1^T * scale   (128x64x64), 8x4 strided fragments
    float s[8][4];
#pragma unroll
    for (int r = 0; r < 8; r++)
#pragma unroll
        for (int c = 0; c < 4; c++) s[r][c] = 0.f;
#pragma unroll 8
    for (int d = 0; d < 64; d++) {
        float qf[8], cf[4];
#pragma unroll
        for (int r = 0; r < 8; r++) qf[r] = sQ[(ty + 16*r) * S2P + d];
#pragma unroll
        for (int c = 0; c < 4; c++) cf[c] = sC1[(tx + 16*c) * S2P + d];
#pragma unroll
        for (int r = 0; r < 8; r++)
#pragma unroll
            for (int c = 0; c < 4; c++) s[r][c] = fmaf(qf[r], cf[c], s[r][c]);
    }

    // exact softmax over a (64 values: 4 per thread x 16 lanes)
#pragma unroll
    for (int r = 0; r < 8; r++) {
        float mt = -1e30f;
#pragma unroll
        for (int c = 0; c < 4; c++) { s[r][c] *= SCALE_; mt = fmaxf(mt, s[r][c]); }
#pragma unroll
        for (int ms = 8; ms >= 1; ms >>= 1)
            mt = fmaxf(mt, __shfl_xor_sync(0xffffffffu, mt, ms));
        float rs = 0.f;
#pragma unroll
        for (int c = 0; c < 4; c++) { s[r][c] = __expf(s[r][c] - mt); rs += s[r][c]; }
#pragma unroll
        for (int ms = 8; ms >= 1; ms >>= 1)
            rs += __shfl_xor_sync(0xffffffffu, rs, ms);
        const float inv = 1.f / rs;
        const int t = t0 + ty + 16*r;
        const size_t so = ((size_t)bh * T_ + t) * 64;
#pragma unroll
        for (int c = 0; c < 4; c++) {
            const float p = s[r][c] * inv;
            sP[(ty + 16*r) * S2P + tx + 16*c] = p;
            s2out[so + tx + 16*c] = p;               // output #2: s2[b,h,t,a]
        }
    }
    __syncthreads();

    // c2 = P @ c1   (128x64x64)
    float acc[8][4];
#pragma unroll
    for (int r = 0; r < 8; r++)
#pragma unroll
        for (int c = 0; c < 4; c++) acc[r][c] = 0.f;
#pragma unroll 8
    for (int a = 0; a < 64; a++) {
        float pf[8], cf[4];
#pragma unroll
        for (int r = 0; r < 8; r++) pf[r] = sP[(ty + 16*r) * S2P + a];
#pragma unroll
        for (int c = 0; c < 4; c++) cf[c] = sC1[a * S2P + tx + 16*c];
#pragma unroll
        for (int r = 0; r < 8; r++)
#pragma unroll
            for (int c = 0; c < 4; c++) acc[r][c] = fmaf(pf[r], cf[c], acc[r][c]);
    }
#pragma unroll
    for (int r = 0; r < 8; r++) {
        const int t = t0 + ty + 16*r;
#pragma unroll
        for (int c = 0; c < 4; c++)
            c2[(size_t)(b * T_ + t) * C_ + h * 64 + tx + 16*c] = acc[r][c];
    }
}

// =====================================================================
// launch
// =====================================================================
extern "C" void kernel_launch(void* const* d_in, const int* in_sizes, int n_in,
                              void* d_out, int out_size)
{
    (void)in_sizes; (void)n_in; (void)out_size;
    const float* x     = (const float*)d_in[0];
    const float* Wqkv  = (const float*)d_in[1];
    const float* bqkv  = (const float*)d_in[2];
    const float* Wq    = (const float*)d_in[3];
    const float* bq    = (const float*)d_in[4];
    const float* Wk    = (const float*)d_in[5];
    const float* bk    = (const float*)d_in[6];
    const float* Wv    = (const float*)d_in[7];
    const float* bv    = (const float*)d_in[8];
    const float* ag    = (const float*)d_in[9];
    const float* Wout  = (const float*)d_in[10];
    const float* bout  = (const float*)d_in[11];
    const float* Wproj = (const float*)d_in[12];
    const float* bproj = (const float*)d_in[13];
    float* out = (float*)d_out;

    float *qkv, *qa, *pm, *pl, *pacc, *c1, *c2, *wcomb, *bcomb;
    cudaGetSymbolAddress((void**)&qkv,   g_qkv);
    cudaGetSymbolAddress((void**)&qa,    g_qa);
    cudaGetSymbolAddress((void**)&pm,    g_pm);
    cudaGetSymbolAddress((void**)&pl,    g_pl);
    cudaGetSymbolAddress((void**)&pacc,  g_pacc);
    cudaGetSymbolAddress((void**)&c1,    g_c1);
    cudaGetSymbolAddress((void**)&c2,    g_c2);
    cudaGetSymbolAddress((void**)&wcomb, g_wcomb);
    cudaGetSymbolAddress((void**)&bcomb, g_bcomb);

    cudaFuncSetAttribute(stage1_kernel, cudaFuncAttributeMaxDynamicSharedMemorySize, S1_SMEM);
    cudaFuncSetAttribute(stage2_kernel, cudaFuncAttributeMaxDynamicSharedMemorySize, S2_SMEM);

    // 1. qkv = x @ Wqkv^T + bqkv                         [16384, 3072]
    gemm_bias_kernel<1><<<dim3(C3_/128, BT_/128), 256>>>(x, Wqkv, bqkv, qkv, BT_, C3_, C_);
    // 2. q_a (per-head, batch-independent), combined bias, combined weight
    qa_kernel<<<NH_, 256>>>(ag, Wq, bq, qa);
    bcomb_kernel<<<C_/256, 256>>>(Wproj, bout, bproj, bcomb);
    gemm_bias_kernel<0><<<dim3(C_/128, C_/128), 256>>>(Wproj, Wout, nullptr, wcomb, C_, C_, C_);
    // 3. stage-1 attention (fused k_a/v_a projections, split-T online softmax)
    stage1_kernel<<<dim3(NCHUNK_, BH_), 256, S1_SMEM>>>(qkv, qa, Wk, bk, Wv, bv, pm, pl, pacc);
    s1combine_kernel<<<BH_, 256>>>(pm, pl, pacc, c1);
    // 4. stage-2 attention -> s2 (output #2) + c2
    stage2_kernel<<<dim3(T_/128, BH_), 256, S2_SMEM>>>(qkv, c1, out + (size_t)BT_ * C_, c2);
    // 5. y = c2 @ (Wproj@Wout)^T + b'  -> output #1
    gemm_bias_kernel<1><<<dim3(C_/128, BT_/128), 256>>>(c2, wcomb, bcomb, out, BT_, C_, C_);
}

// round 7
// speedup vs baseline: 1.4599x; 1.4599x over previous
#include <cuda_runtime.h>
#include <cstdint>

// ---------------- problem constants ----------------
constexpr int B_  = 4;
constexpr int T_  = 4096;
constexpr int C_  = 1024;
constexpr int NH_ = 16;
constexpr int HD_ = 64;
constexpr int A_  = 64;
constexpr int C3_ = 3 * C_;          // 3072
constexpr int BT_ = B_ * T_;         // 16384 rows
constexpr int BH_ = B_ * NH_;        // 64 (b,h) pairs
constexpr int NCHUNK_ = 8;           // T split for stage-1
constexpr int CT_ = T_ / NCHUNK_;    // 512 keys per chunk
constexpr int KT_ = 64;              // key tile
constexpr float SCALE_ = 0.125f;     // 1/sqrt(64)

// ---------------- scratch (device globals: no cudaMalloc allowed) ----------------
__device__ float g_qkv[(size_t)BT_ * C3_];                    // [B*T, 3C]
__device__ float g_qa[NH_ * A_ * HD_];                        // q_a (batch-independent)
__device__ float g_pm[BH_ * NCHUNK_ * A_];                    // stage-1 partial max
__device__ float g_pl[BH_ * NCHUNK_ * A_];                    // stage-1 partial sum
__device__ float g_pacc[(size_t)BH_ * NCHUNK_ * A_ * HD_];    // stage-1 partial acc
__device__ float g_c1[BH_ * A_ * HD_];                        // agent context
__device__ float g_c2[(size_t)BT_ * C_];                      // token context [B*T, C]
__device__ float g_wcomb[C_ * C_];                            // Wproj @ Wout
__device__ float g_bcomb[C_];                                 // Wproj @ bout + bproj

// =====================================================================
// TF32 tensor-core helpers
// =====================================================================
__device__ __forceinline__ void split_tf32(float x, uint32_t& hi, uint32_t& lo) {
    uint32_t h;
    asm("cvt.rna.tf32.f32 %0, %1;" : "=r"(h) : "f"(x));
    float r = x - __uint_as_float(h);     // exact (hi = x rounded to 11 bits)
    uint32_t l;
    asm("cvt.rna.tf32.f32 %0, %1;" : "=r"(l) : "f"(r));
    hi = h; lo = l;
}

__device__ __forceinline__ void mma_tf32(float c[4], const uint32_t a[4], const uint32_t b[2]) {
    asm volatile(
        "mma.sync.aligned.m16n8k8.row.col.f32.tf32.tf32.f32 "
        "{%0,%1,%2,%3}, {%4,%5,%6,%7}, {%8,%9}, {%0,%1,%2,%3};"
        : "+f"(c[0]), "+f"(c[1]), "+f"(c[2]), "+f"(c[3])
        : "r"(a[0]), "r"(a[1]), "r"(a[2]), "r"(a[3]), "r"(b[0]), "r"(b[1]));
}

__device__ __forceinline__ void cp_async16(uint32_t saddr, const void* gaddr) {
    asm volatile("cp.async.cg.shared.global [%0], [%1], 16;" :: "r"(saddr), "l"(gaddr));
}

// =====================================================================
// TF32 split GEMM:  C[M,N] = A[M,K] @ op(B) + bias   (fp32-accuracy via 3xTF32)
//   BTR=1 : B is [N,K] row-major (C = A @ B^T)
//   BTR=0 : B is [K,N] row-major (C = A @ B)
// BM=BN=128, BK=32, 256 threads (8 warps, 2x4), warp tile 64x32.
// smem strides: A/B(BTR1): 36 words/row -> frag banks 4g+c (conflict-free)
//               B(BTR0):  136 words/row -> frag banks 8c+g (conflict-free)
// Double-buffered cp.async pipeline. All shapes multiples of tiles.
// =====================================================================
constexpr int G_ASTR = 36;
constexpr int G_BSTR0 = 136;
constexpr int G_ATILE = 128 * G_ASTR;      // 4608 floats
constexpr int G_STAGE = G_ATILE * 2;       // A + B per stage (B uses <= 4608)
constexpr int G_SMEM = 2 * G_STAGE * (int)sizeof(float);   // 73728 B

template<int BTR>
__device__ __forceinline__ void g_load_tile(const float* __restrict__ A,
                                            const float* __restrict__ Bm,
                                            float* sA, float* sB,
                                            int N, int K, int m0, int n0, int k0, int tid)
{
#pragma unroll
    for (int q = 0; q < 4; q++) {               // A tile: 128 rows x 32 k
        const int chunk = tid + q * 256;
        const int row = chunk >> 3, c16 = chunk & 7;
        cp_async16((uint32_t)__cvta_generic_to_shared(sA + row * G_ASTR + c16 * 4),
                   A + (size_t)(m0 + row) * K + k0 + c16 * 4);
    }
    if (BTR) {
#pragma unroll
        for (int q = 0; q < 4; q++) {           // B tile: 128 n-rows x 32 k
            const int chunk = tid + q * 256;
            const int row = chunk >> 3, c16 = chunk & 7;
            cp_async16((uint32_t)__cvta_generic_to_shared(sB + row * G_ASTR + c16 * 4),
                       Bm + (size_t)(n0 + row) * K + k0 + c16 * 4);
        }
    } else {
#pragma unroll
        for (int q = 0; q < 4; q++) {           // B tile: 32 k-rows x 128 n
            const int chunk = tid + q * 256;
            const int row = chunk >> 5, c16 = chunk & 31;
            cp_async16((uint32_t)__cvta_generic_to_shared(sB + row * G_BSTR0 + c16 * 4),
                       Bm + (size_t)(k0 + row) * N + n0 + c16 * 4);
        }
    }
}

template<int BTR>
__global__ __launch_bounds__(256)
void gemm_tf32_kernel(const float* __restrict__ A, const float* __restrict__ Bm,
                      const float* __restrict__ bias, float* __restrict__ Cm,
                      int M, int N, int K)
{
    extern __shared__ float gsm[];
    const int tid = threadIdx.x;
    const int warp = tid >> 5, lane = tid & 31;
    const int g = lane >> 2, c = lane & 3;       // groupID / thread-in-group
    const int m0w = (warp >> 2) * 64;            // warp M offset within block
    const int n0w = (warp & 3) * 32;             // warp N offset within block
    const int m0 = blockIdx.y * 128, n0 = blockIdx.x * 128;

    float acc[4][4][4];
#pragma unroll
    for (int mf = 0; mf < 4; mf++)
#pragma unroll
        for (int nf = 0; nf < 4; nf++)
#pragma unroll
            for (int i = 0; i < 4; i++) acc[mf][nf][i] = 0.f;

    const int nk = K >> 5;

    g_load_tile<BTR>(A, Bm, gsm, gsm + G_ATILE, N, K, m0, n0, 0, tid);
    asm volatile("cp.async.commit_group;");

    for (int kt = 0; kt < nk; kt++) {
        float* sA = gsm + (kt & 1) * G_STAGE;
        float* sB = sA + G_ATILE;
        if (kt + 1 < nk) {
            float* sAn = gsm + ((kt + 1) & 1) * G_STAGE;
            g_load_tile<BTR>(A, Bm, sAn, sAn + G_ATILE, N, K, m0, n0, (kt + 1) * 32, tid);
            asm volatile("cp.async.commit_group;");
            asm volatile("cp.async.wait_group 1;");
        } else {
            asm volatile("cp.async.wait_group 0;");
        }
        __syncthreads();

#pragma unroll
        for (int ks = 0; ks < 4; ks++) {
            const int kb = ks * 8;
            // B fragments (hi/lo)
            uint32_t bhi[4][2], blo[4][2];
#pragma unroll
            for (int nf = 0; nf < 4; nf++)
#pragma unroll
                for (int i = 0; i < 2; i++) {
                    const float bv = BTR
                        ? sB[(n0w + nf * 8 + g) * G_ASTR + kb + c + i * 4]
                        : sB[(kb + c + i * 4) * G_BSTR0 + n0w + nf * 8 + g];
                    split_tf32(bv, bhi[nf][i], blo[nf][i]);
                }
#pragma unroll
            for (int mf = 0; mf < 4; mf++) {
                uint32_t ahi[4], alo[4];
#pragma unroll
                for (int i = 0; i < 4; i++) {
                    const int r = m0w + mf * 16 + g + (i & 1) * 8;
                    const int cc = kb + c + (i >> 1) * 4;
                    split_tf32(sA[r * G_ASTR + cc], ahi[i], alo[i]);
                }
#pragma unroll
                for (int nf = 0; nf < 4; nf++) {
                    mma_tf32(acc[mf][nf], ahi, bhi[nf]);
                    mma_tf32(acc[mf][nf], alo, bhi[nf]);
                    mma_tf32(acc[mf][nf], ahi, blo[nf]);
                }
            }
        }
        __syncthreads();
    }

    // epilogue
#pragma unroll
    for (int nf = 0; nf < 4; nf++) {
        const int col = n0 + n0w + nf * 8 + 2 * c;
        const float b0 = bias ? bias[col] : 0.f;
        const float b1 = bias ? bias[col + 1] : 0.f;
#pragma unroll
        for (int mf = 0; mf < 4; mf++) {
            const int r0 = m0 + m0w + mf * 16 + g;
            float2 v0 = make_float2(acc[mf][nf][0] + b0, acc[mf][nf][1] + b1);
            float2 v1 = make_float2(acc[mf][nf][2] + b0, acc[mf][nf][3] + b1);
            *reinterpret_cast<float2*>(Cm + (size_t)r0 * N + col) = v0;
            *reinterpret_cast<float2*>(Cm + (size_t)(r0 + 8) * N + col) = v1;
        }
    }
}

// =====================================================================
// q_a[h] = agent_tokens[h] @ Wq^T + bq   (batch-independent)
// =====================================================================
__global__ __launch_bounds__(256)
void qa_kernel(const float* __restrict__ ag, const float* __restrict__ Wq,
               const float* __restrict__ bq, float* __restrict__ qa)
{
    __shared__ float sA[64 * 65];
    __shared__ float sW[64 * 65];
    const int tid = threadIdx.x;
    const int tx = tid & 15, ty = tid >> 4;
    const int h = blockIdx.x;

    for (int idx = tid; idx < 4096; idx += 256) {
        sA[(idx >> 6) * 65 + (idx & 63)] = ag[h * 4096 + idx];
        sW[(idx >> 6) * 65 + (idx & 63)] = Wq[idx];
    }
    __syncthreads();

    float acc[4][4];
#pragma unroll
    for (int r = 0; r < 4; r++)
#pragma unroll
        for (int c = 0; c < 4; c++) acc[r][c] = bq[tx + 16*c];
#pragma unroll 8
    for (int e = 0; e < 64; e++) {
        float af[4], wf[4];
#pragma unroll
        for (int r = 0; r < 4; r++) af[r] = sA[(ty + 16*r) * 65 + e];
#pragma unroll
        for (int c = 0; c < 4; c++) wf[c] = sW[(tx + 16*c) * 65 + e];
#pragma unroll
        for (int r = 0; r < 4; r++)
#pragma unroll
            for (int c = 0; c < 4; c++) acc[r][c] = fmaf(af[r], wf[c], acc[r][c]);
    }
#pragma unroll
    for (int r = 0; r < 4; r++)
#pragma unroll
        for (int c = 0; c < 4; c++)
            qa[h * 4096 + (ty + 16*r) * 64 + tx + 16*c] = acc[r][c];
}

// b' = Wproj @ bout + bproj
__global__ void bcomb_kernel(const float* __restrict__ Wproj, const float* __restrict__ bout,
                             const float* __restrict__ bproj, float* __restrict__ bcomb)
{
    const int i = blockIdx.x * 256 + threadIdx.x;
    float s = bproj[i];
    for (int k = 0; k < C_; k++) s = fmaf(Wproj[(size_t)i * C_ + k], bout[k], s);
    bcomb[i] = s;
}

// =====================================================================
// Stage 1 (fused): per (b,h,chunk) block.  (unchanged from round 2)
// =====================================================================
constexpr int S1P = 65;
constexpr int S1_SMEM = 6 * 64 * S1P * (int)sizeof(float);   // 99840 B

__global__ __launch_bounds__(256)
void stage1_kernel(const float* __restrict__ qkv, const float* __restrict__ qa,
                   const float* __restrict__ Wk, const float* __restrict__ bk,
                   const float* __restrict__ Wv, const float* __restrict__ bv,
                   float* __restrict__ pm, float* __restrict__ pl,
                   float* __restrict__ pacc)
{
    extern __shared__ float sm1[];
    float* sQa = sm1;
    float* sWk = sQa + 64 * S1P;
    float* sWv = sWk + 64 * S1P;
    float* sX  = sWv + 64 * S1P;
    float* sY  = sX  + 64 * S1P;
    float* sP  = sY  + 64 * S1P;

    const int tid = threadIdx.x;
    const int tx = tid & 15, ty = tid >> 4;
    const int chunk = blockIdx.x, bh = blockIdx.y;
    const int b = bh >> 4, h = bh & 15;

    for (int idx = tid; idx < 4096; idx += 256) {
        const int r = idx >> 6, cc = idx & 63;
        sQa[r * S1P + cc] = qa[h * 4096 + idx];
        sWk[r * S1P + cc] = Wk[idx];
        sWv[r * S1P + cc] = Wv[idx];
    }
    float bkr[4], bvr[4];
#pragma unroll
    for (int c = 0; c < 4; c++) { bkr[c] = bk[tx + 16*c]; bvr[c] = bv[tx + 16*c]; }

    float m_run[4], l_run[4], acc[4][4];
#pragma unroll
    for (int r = 0; r < 4; r++) {
        m_run[r] = -1e30f; l_run[r] = 0.f;
#pragma unroll
        for (int c = 0; c < 4; c++) acc[r][c] = 0.f;
    }

    const size_t rowbase = (size_t)(b * T_) * C3_;

    for (int kt = 0; kt < CT_ / KT_; kt++) {
        const int t0 = chunk * CT_ + kt * KT_;

        for (int idx = tid; idx < 1024; idx += 256) {
            const int row = idx >> 4, c4 = idx & 15;
            const float4 v = *reinterpret_cast<const float4*>(
                qkv + rowbase + (size_t)(t0 + row) * C3_ + C_ + h * 64 + c4 * 4);
            float* d = &sX[row * S1P + c4 * 4];
            d[0] = v.x; d[1] = v.y; d[2] = v.z; d[3] = v.w;
        }
        __syncthreads();

        {
            float ka[4][4];
#pragma unroll
            for (int r = 0; r < 4; r++)
#pragma unroll
                for (int c = 0; c < 4; c++) ka[r][c] = bkr[c];
#pragma unroll 8
            for (int e = 0; e < 64; e++) {
                float xa[4], wb[4];
#pragma unroll
                for (int r = 0; r < 4; r++) xa[r] = sX[(ty + 16*r) * S1P + e];
#pragma unroll
                for (int c = 0; c < 4; c++) wb[c] = sWk[(tx + 16*c) * S1P + e];
#pragma unroll
                for (int r = 0; r < 4; r++)
#pragma unroll
                    for (int c = 0; c < 4; c++) ka[r][c] = fmaf(xa[r], wb[c], ka[r][c]);
            }
#pragma unroll
            for (int r = 0; r < 4; r++)
#pragma unroll
                for (int c = 0; c < 4; c++)
                    sY[(ty + 16*r) * S1P + tx + 16*c] = ka[r][c];
        }
        __syncthreads();

        for (int idx = tid; idx < 1024; idx += 256) {
            const int row = idx >> 4, c4 = idx & 15;
            const float4 v = *reinterpret_cast<const float4*>(
                qkv + rowbase + (size_t)(t0 + row) * C3_ + 2 * C_ + h * 64 + c4 * 4);
            float* d = &sX[row * S1P + c4 * 4];
            d[0] = v.x; d[1] = v.y; d[2] = v.z; d[3] = v.w;
        }

        {
            float s[4][4];
#pragma unroll
            for (int r = 0; r < 4; r++)
#pragma unroll
                for (int c = 0; c < 4; c++) s[r][c] = 0.f;
#pragma unroll 8
            for (int e = 0; e < 64; e++) {
                float qf[4], kf[4];
#pragma unroll
                for (int r = 0; r < 4; r++) qf[r] = sQa[(ty + 16*r) * S1P + e];
#pragma unroll
                for (int c = 0; c < 4; c++) kf[c] = sY[(tx + 16*c) * S1P + e];
#pragma unroll
                for (int r = 0; r < 4; r++)
#pragma unroll
                    for (int c = 0; c < 4; c++) s[r][c] = fmaf(qf[r], kf[c], s[r][c]);
            }
#pragma unroll
            for (int r = 0; r < 4; r++) {
                float mt = -1e30f;
#pragma unroll
                for (int c = 0; c < 4; c++) { s[r][c] *= SCALE_; mt = fmaxf(mt, s[r][c]); }
#pragma unroll
                for (int ms = 8; ms >= 1; ms >>= 1)
                    mt = fmaxf(mt, __shfl_xor_sync(0xffffffffu, mt, ms));
                const float mn = fmaxf(m_run[r], mt);
                const float corr = __expf(m_run[r] - mn);
                float rs = 0.f;
#pragma unroll
                for (int c = 0; c < 4; c++) {
                    const float p = __expf(s[r][c] - mn);
                    sP[(ty + 16*r) * S1P + tx + 16*c] = p;
                    rs += p;
                }
#pragma unroll
                for (int ms = 8; ms >= 1; ms >>= 1)
                    rs += __shfl_xor_sync(0xffffffffu, rs, ms);
                l_run[r] = l_run[r] * corr + rs;
                m_run[r] = mn;
#pragma unroll
                for (int c = 0; c < 4; c++) acc[r][c] *= corr;
            }
        }
        __syncthreads();

        {
            float va[4][4];
#pragma unroll
            for (int r = 0; r < 4; r++)
#pragma unroll
                for (int c = 0; c < 4; c++) va[r][c] = bvr[c];
#pragma unroll 8
            for (int e = 0; e < 64; e++) {
                float xa[4], wb[4];
#pragma unroll
                for (int r = 0; r < 4; r++) xa[r] = sX[(ty + 16*r) * S1P + e];
#pragma unroll
                for (int c = 0; c < 4; c++) wb[c] = sWv[(tx + 16*c) * S1P + e];
#pragma unroll
                for (int r = 0; r < 4; r++)
#pragma unroll
                    for (int c = 0; c < 4; c++) va[r][c] = fmaf(xa[r], wb[c], va[r][c]);
            }
#pragma unroll
            for (int r = 0; r < 4; r++)
#pragma unroll
                for (int c = 0; c < 4; c++)
                    sY[(ty + 16*r) * S1P + tx + 16*c] = va[r][c];
        }
        __syncthreads();

#pragma unroll 8
        for (int t = 0; t < 64; t++) {
            float pf[4], vf[4];
#pragma unroll
            for (int r = 0; r < 4; r++) pf[r] = sP[(ty + 16*r) * S1P + t];
#pragma unroll
            for (int c = 0; c < 4; c++) vf[c] = sY[t * S1P + tx + 16*c];
#pragma unroll
            for (int r = 0; r < 4; r++)
#pragma unroll
                for (int c = 0; c < 4; c++) acc[r][c] = fmaf(pf[r], vf[c], acc[r][c]);
        }
    }

    const int pi = bh * NCHUNK_ + chunk;
    if (tx == 0) {
#pragma unroll
        for (int r = 0; r < 4; r++) {
            pm[pi * 64 + ty + 16*r] = m_run[r];
            pl[pi * 64 + ty + 16*r] = l_run[r];
        }
    }
#pragma unroll
    for (int r = 0; r < 4; r++)
#pragma unroll
        for (int c = 0; c < 4; c++)
            pacc[(size_t)pi * 4096 + (ty + 16*r) * 64 + tx + 16*c] = acc[r][c];
}

// combine split-T partials -> c1[b,h,a,d]
__global__ __launch_bounds__(256)
void s1combine_kernel(const float* __restrict__ pm, const float* __restrict__ pl,
                      const float* __restrict__ pacc, float* __restrict__ c1)
{
    const int bh = blockIdx.x;
    const int tid = threadIdx.x;
    const int a = tid >> 2, dg = tid & 3;

    float mc[NCHUNK_], lc[NCHUNK_];
    float m = -1e30f;
#pragma unroll
    for (int c = 0; c < NCHUNK_; c++) {
        mc[c] = pm[(bh * NCHUNK_ + c) * 64 + a];
        lc[c] = pl[(bh * NCHUNK_ + c) * 64 + a];
        m = fmaxf(m, mc[c]);
    }
    float l = 0.f, w[NCHUNK_];
#pragma unroll
    for (int c = 0; c < NCHUNK_; c++) { w[c] = __expf(mc[c] - m); l += lc[c] * w[c]; }
    const float inv = 1.f / l;
#pragma unroll
    for (int j = 0; j < 16; j++) {
        const int d = dg * 16 + j;
        float s = 0.f;
#pragma unroll
        for (int c = 0; c < NCHUNK_; c++)
            s += pacc[(size_t)(bh * NCHUNK_ + c) * 4096 + a * 64 + d] * w[c];
        c1[bh * 4096 + a * 64 + d] = s * inv;
    }
}

// =====================================================================
// Stage 2 (unchanged): per (b,h, 128-token tile). Emits s2 + c2.
// =====================================================================
constexpr int S2P = 65;
constexpr int S2_SMEM = (64 + 128 + 128) * S2P * (int)sizeof(float);  // 83200 B

__global__ __launch_bounds__(256)
void stage2_kernel(const float* __restrict__ qkv, const float* __restrict__ c1,
                   float* __restrict__ s2out, float* __restrict__ c2)
{
    extern __shared__ float sm2[];
    float* sC1 = sm2;
    float* sQ  = sC1 + 64 * S2P;
    float* sP  = sQ + 128 * S2P;

    const int tid = threadIdx.x;
    const int tx = tid & 15, ty = tid >> 4;
    const int bh = blockIdx.y;
    const int b = bh >> 4, h = bh & 15;
    const int t0 = blockIdx.x * 128;

    for (int idx = tid; idx < 4096; idx += 256)
        sC1[(idx >> 6) * S2P + (idx & 63)] = c1[bh * 4096 + idx];
    for (int idx = tid; idx < 2048; idx += 256) {
        const int row = idx >> 4, c4 = idx & 15;
        const float4 v = *reinterpret_cast<const float4*>(
            qkv + (size_t)(b * T_ + t0 + row) * C3_ + h * 64 + c4 * 4);
        float* d = &sQ[row * S2P + c4 * 4];
        d[0] = v.x; d[1] = v.y; d[2] = v.z; d[3] = v.w;
    }
    __syncthreads();

    float s[8][4];
#pragma unroll
    for (int r = 0; r < 8; r++)
#pragma unroll
        for (int c = 0; c < 4; c++) s[r][c] = 0.f;
#pragma unroll 8
    for (int d = 0; d < 64; d++) {
        float qf[8], cf[4];
#pragma unroll
        for (int r = 0; r < 8; r++) qf[r] = sQ[(ty + 16*r) * S2P + d];
#pragma unroll
        for (int c = 0; c < 4; c++) cf[c] = sC1[(tx + 16*c) * S2P + d];
#pragma unroll
        for (int r = 0; r < 8; r++)
#pragma unroll
            for (int c = 0; c < 4; c++) s[r][c] = fmaf(qf[r], cf[c], s[r][c]);
    }

#pragma unroll
    for (int r = 0; r < 8; r++) {
        float mt = -1e30f;
#pragma unroll
        for (int c = 0; c < 4; c++) { s[r][c] *= SCALE_; mt = fmaxf(mt, s[r][c]); }
#pragma unroll
        for (int ms = 8; ms >= 1; ms >>= 1)
            mt = fmaxf(mt, __shfl_xor_sync(0xffffffffu, mt, ms));
        float rs = 0.f;
#pragma unroll
        for (int c = 0; c < 4; c++) { s[r][c] = __expf(s[r][c] - mt); rs += s[r][c]; }
#pragma unroll
        for (int ms = 8; ms >= 1; ms >>= 1)
            rs += __shfl_xor_sync(0xffffffffu, rs, ms);
        const float inv = 1.f / rs;
        const int t = t0 + ty + 16*r;
        const size_t so = ((size_t)bh * T_ + t) * 64;
#pragma unroll
        for (int c = 0; c < 4; c++) {
            const float p = s[r][c] * inv;
            sP[(ty + 16*r) * S2P + tx + 16*c] = p;
            s2out[so + tx + 16*c] = p;
        }
    }
    __syncthreads();

    float acc[8][4];
#pragma unroll
    for (int r = 0; r < 8; r++)
#pragma unroll
        for (int c = 0; c < 4; c++) acc[r][c] = 0.f;
#pragma unroll 8
    for (int a = 0; a < 64; a++) {
        float pf[8], cf[4];
#pragma unroll
        for (int r = 0; r < 8; r++) pf[r] = sP[(ty + 16*r) * S2P + a];
#pragma unroll
        for (int c = 0; c < 4; c++) cf[c] = sC1[a * S2P + tx + 16*c];
#pragma unroll
        for (int r = 0; r < 8; r++)
#pragma unroll
            for (int c = 0; c < 4; c++) acc[r][c] = fmaf(pf[r], cf[c], acc[r][c]);
    }
#pragma unroll
    for (int r = 0; r < 8; r++) {
        const int t = t0 + ty + 16*r;
#pragma unroll
        for (int c = 0; c < 4; c++)
            c2[(size_t)(b * T_ + t) * C_ + h * 64 + tx + 16*c] = acc[r][c];
    }
}

// =====================================================================
// launch
// =====================================================================
extern "C" void kernel_launch(void* const* d_in, const int* in_sizes, int n_in,
                              void* d_out, int out_size)
{
    (void)in_sizes; (void)n_in; (void)out_size;
    const float* x     = (const float*)d_in[0];
    const float* Wqkv  = (const float*)d_in[1];
    const float* bqkv  = (const float*)d_in[2];
    const float* Wq    = (const float*)d_in[3];
    const float* bq    = (const float*)d_in[4];
    const float* Wk    = (const float*)d_in[5];
    const float* bk    = (const float*)d_in[6];
    const float* Wv    = (const float*)d_in[7];
    const float* bv    = (const float*)d_in[8];
    const float* ag    = (const float*)d_in[9];
    const float* Wout  = (const float*)d_in[10];
    const float* bout  = (const float*)d_in[11];
    const float* Wproj = (const float*)d_in[12];
    const float* bproj = (const float*)d_in[13];
    float* out = (float*)d_out;

    float *qkv, *qa, *pm, *pl, *pacc, *c1, *c2, *wcomb, *bcomb;
    cudaGetSymbolAddress((void**)&qkv,   g_qkv);
    cudaGetSymbolAddress((void**)&qa,    g_qa);
    cudaGetSymbolAddress((void**)&pm,    g_pm);
    cudaGetSymbolAddress((void**)&pl,    g_pl);
    cudaGetSymbolAddress((void**)&pacc,  g_pacc);
    cudaGetSymbolAddress((void**)&c1,    g_c1);
    cudaGetSymbolAddress((void**)&c2,    g_c2);
    cudaGetSymbolAddress((void**)&wcomb, g_wcomb);
    cudaGetSymbolAddress((void**)&bcomb, g_bcomb);

    cudaFuncSetAttribute(gemm_tf32_kernel<1>, cudaFuncAttributeMaxDynamicSharedMemorySize, G_SMEM);
    cudaFuncSetAttribute(gemm_tf32_kernel<0>, cudaFuncAttributeMaxDynamicSharedMemorySize, G_SMEM);
    cudaFuncSetAttribute(stage1_kernel, cudaFuncAttributeMaxDynamicSharedMemorySize, S1_SMEM);
    cudaFuncSetAttribute(stage2_kernel, cudaFuncAttributeMaxDynamicSharedMemorySize, S2_SMEM);

    // 1. qkv = x @ Wqkv^T + bqkv                         [16384, 3072]
    gemm_tf32_kernel<1><<<dim3(C3_/128, BT_/128), 256, G_SMEM>>>(x, Wqkv, bqkv, qkv, BT_, C3_, C_);
    // 2. q_a (per-head), combined bias, combined weight wcomb = Wproj @ Wout
    qa_kernel<<<NH_, 256>>>(ag, Wq, bq, qa);
    bcomb_kernel<<<C_/256, 256>>>(Wproj, bout, bproj, bcomb);
    gemm_tf32_kernel<0><<<dim3(C_/128, C_/128), 256, G_SMEM>>>(Wproj, Wout, nullptr, wcomb, C_, C_, C_);
    // 3. stage-1 attention (fused k_a/v_a projections, split-T online softmax)
    stage1_kernel<<<dim3(NCHUNK_, BH_), 256, S1_SMEM>>>(qkv, qa, Wk, bk, Wv, bv, pm, pl, pacc);
    s1combine_kernel<<<BH_, 256>>>(pm, pl, pacc, c1);
    // 4. stage-2 attention -> s2 (output #2) + c2
    stage2_kernel<<<dim3(T_/128, BH_), 256, S2_SMEM>>>(qkv, c1, out + (size_t)BT_ * C_, c2);
    // 5. y = c2 @ (Wproj@Wout)^T + b'  -> output #1
    gemm_tf32_kernel<1><<<dim3(C_/128, BT_/128), 256, G_SMEM>>>(c2, wcomb, bcomb, out, BT_, C_, C_);
}

// round 12
// speedup vs baseline: 1.5156x; 1.0381x over previous
#include <cuda_runtime.h>
#include <cstdint>

// ---------------- problem constants ----------------
constexpr int B_  = 4;
constexpr int T_  = 4096;
constexpr int C_  = 1024;
constexpr int NH_ = 16;
constexpr int HD_ = 64;
constexpr int A_  = 64;
constexpr int C3_ = 3 * C_;          // 3072
constexpr int BT_ = B_ * T_;         // 16384 rows
constexpr int BH_ = B_ * NH_;        // 64 (b,h) pairs
constexpr int NCHUNK_ = 8;           // T split for stage-1
constexpr int CT_ = T_ / NCHUNK_;    // 512 keys per chunk
constexpr int KT_ = 64;              // key tile
constexpr float SCALE_ = 0.125f;     // 1/sqrt(64)

// ---------------- scratch (device globals: no cudaMalloc allowed) ----------------
__device__ float g_qkv[(size_t)BT_ * C3_];                    // [B*T, 3C] = q | k_a | v_a
__device__ float g_w2[(size_t)C3_ * C_];                      // folded Wqkv
__device__ float g_b2[C3_];                                   // folded bqkv
__device__ float g_qa[NH_ * A_ * HD_];                        // q_a (batch-independent)
__device__ float g_pm[BH_ * NCHUNK_ * A_];                    // stage-1 partial max
__device__ float g_pl[BH_ * NCHUNK_ * A_];                    // stage-1 partial sum
__device__ float g_pacc[(size_t)BH_ * NCHUNK_ * A_ * HD_];    // stage-1 partial acc
__device__ float g_c1[BH_ * A_ * HD_];                        // agent context
__device__ float g_c2[(size_t)BT_ * C_];                      // token context [B*T, C]
__device__ float g_wcomb[C_ * C_];                            // Wproj @ Wout
__device__ float g_bcomb[C_];                                 // Wproj @ bout + bproj

// =====================================================================
// TF32 tensor-core helpers
// =====================================================================
__device__ __forceinline__ void split_tf32(float x, uint32_t& hi, uint32_t& lo) {
    uint32_t h;
    asm("cvt.rna.tf32.f32 %0, %1;" : "=r"(h) : "f"(x));
    float r = x - __uint_as_float(h);     // exact (hi = x rounded to 11 bits)
    uint32_t l;
    asm("cvt.rna.tf32.f32 %0, %1;" : "=r"(l) : "f"(r));
    hi = h; lo = l;
}

__device__ __forceinline__ void mma_tf32(float c[4], const uint32_t a[4], const uint32_t b[2]) {
    asm volatile(
        "mma.sync.aligned.m16n8k8.row.col.f32.tf32.tf32.f32 "
        "{%0,%1,%2,%3}, {%4,%5,%6,%7}, {%8,%9}, {%0,%1,%2,%3};"
        : "+f"(c[0]), "+f"(c[1]), "+f"(c[2]), "+f"(c[3])
        : "r"(a[0]), "r"(a[1]), "r"(a[2]), "r"(a[3]), "r"(b[0]), "r"(b[1]));
}

__device__ __forceinline__ void cp_async16(uint32_t saddr, const void* gaddr) {
    asm volatile("cp.async.cg.shared.global [%0], [%1], 16;" :: "r"(saddr), "l"(gaddr));
}

// =====================================================================
// TF32 split GEMM:  C[M,N] = A[M,K] @ op(B) + bias   (fp32-accuracy via 3xTF32)
//   BTR=1 : B is [N,K] row-major (C = A @ B^T)
//   BTR=0 : B is [K,N] row-major (C = A @ B)
// BM=BN=128, BK=32, 256 threads (8 warps, 2x4), warp tile 64x32.
// =====================================================================
constexpr int G_ASTR = 36;
constexpr int G_BSTR0 = 136;
constexpr int G_ATILE = 128 * G_ASTR;      // 4608 floats
constexpr int G_STAGE = G_ATILE * 2;
constexpr int G_SMEM = 2 * G_STAGE * (int)sizeof(float);   // 73728 B

template<int BTR>
__device__ __forceinline__ void g_load_tile(const float* __restrict__ A,
                                            const float* __restrict__ Bm,
                                            float* sA, float* sB,
                                            int N, int K, int m0, int n0, int k0, int tid)
{
#pragma unroll
    for (int q = 0; q < 4; q++) {               // A tile: 128 rows x 32 k
        const int chunk = tid + q * 256;
        const int row = chunk >> 3, c16 = chunk & 7;
        cp_async16((uint32_t)__cvta_generic_to_shared(sA + row * G_ASTR + c16 * 4),
                   A + (size_t)(m0 + row) * K + k0 + c16 * 4);
    }
    if (BTR) {
#pragma unroll
        for (int q = 0; q < 4; q++) {           // B tile: 128 n-rows x 32 k
            const int chunk = tid + q * 256;
            const int row = chunk >> 3, c16 = chunk & 7;
            cp_async16((uint32_t)__cvta_generic_to_shared(sB + row * G_ASTR + c16 * 4),
                       Bm + (size_t)(n0 + row) * K + k0 + c16 * 4);
        }
    } else {
#pragma unroll
        for (int q = 0; q < 4; q++) {           // B tile: 32 k-rows x 128 n
            const int chunk = tid + q * 256;
            const int row = chunk >> 5, c16 = chunk & 31;
            cp_async16((uint32_t)__cvta_generic_to_shared(sB + row * G_BSTR0 + c16 * 4),
                       Bm + (size_t)(k0 + row) * N + n0 + c16 * 4);
        }
    }
}

template<int BTR>
__global__ __launch_bounds__(256)
void gemm_tf32_kernel(const float* __restrict__ A, const float* __restrict__ Bm,
                      const float* __restrict__ bias, float* __restrict__ Cm,
                      int M, int N, int K)
{
    extern __shared__ float gsm[];
    const int tid = threadIdx.x;
    const int warp = tid >> 5, lane = tid & 31;
    const int g = lane >> 2, c = lane & 3;
    const int m0w = (warp >> 2) * 64;
    const int n0w = (warp & 3) * 32;
    const int m0 = blockIdx.y * 128, n0 = blockIdx.x * 128;

    float acc[4][4][4];
#pragma unroll
    for (int mf = 0; mf < 4; mf++)
#pragma unroll
        for (int nf = 0; nf < 4; nf++)
#pragma unroll
            for (int i = 0; i < 4; i++) acc[mf][nf][i] = 0.f;

    const int nk = K >> 5;

    g_load_tile<BTR>(A, Bm, gsm, gsm + G_ATILE, N, K, m0, n0, 0, tid);
    asm volatile("cp.async.commit_group;");

    for (int kt = 0; kt < nk; kt++) {
        float* sA = gsm + (kt & 1) * G_STAGE;
        float* sB = sA + G_ATILE;
        if (kt + 1 < nk) {
            float* sAn = gsm + ((kt + 1) & 1) * G_STAGE;
            g_load_tile<BTR>(A, Bm, sAn, sAn + G_ATILE, N, K, m0, n0, (kt + 1) * 32, tid);
            asm volatile("cp.async.commit_group;");
            asm volatile("cp.async.wait_group 1;");
        } else {
            asm volatile("cp.async.wait_group 0;");
        }
        __syncthreads();

#pragma unroll
        for (int ks = 0; ks < 4; ks++) {
            const int kb = ks * 8;
            uint32_t bhi[4][2], blo[4][2];
#pragma unroll
            for (int nf = 0; nf < 4; nf++)
#pragma unroll
                for (int i = 0; i < 2; i++) {
                    const float bv = BTR
                        ? sB[(n0w + nf * 8 + g) * G_ASTR + kb + c + i * 4]
                        : sB[(kb + c + i * 4) * G_BSTR0 + n0w + nf * 8 + g];
                    split_tf32(bv, bhi[nf][i], blo[nf][i]);
                }
#pragma unroll
            for (int mf = 0; mf < 4; mf++) {
                uint32_t ahi[4], alo[4];
#pragma unroll
                for (int i = 0; i < 4; i++) {
                    const int r = m0w + mf * 16 + g + (i & 1) * 8;
                    const int cc = kb + c + (i >> 1) * 4;
                    split_tf32(sA[r * G_ASTR + cc], ahi[i], alo[i]);
                }
#pragma unroll
                for (int nf = 0; nf < 4; nf++) {
                    mma_tf32(acc[mf][nf], ahi, bhi[nf]);
                    mma_tf32(acc[mf][nf], alo, bhi[nf]);
                    mma_tf32(acc[mf][nf], ahi, blo[nf]);
                }
            }
        }
        __syncthreads();
    }

#pragma unroll
    for (int nf = 0; nf < 4; nf++) {
        const int col = n0 + n0w + nf * 8 + 2 * c;
        const float b0 = bias ? bias[col] : 0.f;
        const float b1 = bias ? bias[col + 1] : 0.f;
#pragma unroll
        for (int mf = 0; mf < 4; mf++) {
            const int r0 = m0 + m0w + mf * 16 + g;
            float2 v0 = make_float2(acc[mf][nf][0] + b0, acc[mf][nf][1] + b1);
            float2 v1 = make_float2(acc[mf][nf][2] + b0, acc[mf][nf][3] + b1);
            *reinterpret_cast<float2*>(Cm + (size_t)r0 * N + col) = v0;
            *reinterpret_cast<float2*>(Cm + (size_t)(r0 + 8) * N + col) = v1;
        }
    }
}

// =====================================================================
// Weight folding: W2 K/V sections = per-head Wk/Wv @ Wqkv block
// grid (C_/64, 2*NH_), by = kv*NH_ + h
// =====================================================================
__global__ __launch_bounds__(256)
void wfold_kernel(const float* __restrict__ Wqkv, const float* __restrict__ Wk,
                  const float* __restrict__ Wv, float* __restrict__ W2)
{
    __shared__ float sW[64 * 65];   // Wk or Wv (d,e)
    __shared__ float sQ[64 * 65];   // Wqkv block (e,j)
    const int tid = threadIdx.x;
    const int tx = tid & 15, ty = tid >> 4;
    const int j0 = blockIdx.x * 64;
    const int sec = blockIdx.y;
    const int kv = sec >> 4, h = sec & 15;
    const float* Wsub = kv ? Wv : Wk;
    const size_t rowbase = (size_t)(C_ + kv * C_ + h * 64);

    for (int idx = tid; idx < 4096; idx += 256) {
        const int r = idx >> 6, cc = idx & 63;
        sW[r * 65 + cc] = Wsub[idx];
        sQ[r * 65 + cc] = Wqkv[(rowbase + r) * C_ + j0 + cc];
    }
    __syncthreads();

    float acc[4][4];
#pragma unroll
    for (int r = 0; r < 4; r++)
#pragma unroll
        for (int c = 0; c < 4; c++) acc[r][c] = 0.f;
#pragma unroll 8
    for (int e = 0; e < 64; e++) {
        float wf[4], qf[4];
#pragma unroll
        for (int r = 0; r < 4; r++) wf[r] = sW[(ty + 16*r) * 65 + e];
#pragma unroll
        for (int c = 0; c < 4; c++) qf[c] = sQ[e * 65 + tx + 16*c];
#pragma unroll
        for (int r = 0; r < 4; r++)
#pragma unroll
            for (int c = 0; c < 4; c++) acc[r][c] = fmaf(wf[r], qf[c], acc[r][c]);
    }
#pragma unroll
    for (int r = 0; r < 4; r++)
#pragma unroll
        for (int c = 0; c < 4; c++)
            W2[(rowbase + ty + 16*r) * C_ + j0 + tx + 16*c] = acc[r][c];
}

// copy Q section of Wqkv into W2 (rows 0..C)
__global__ void copyq_kernel(const float* __restrict__ Wqkv, float* __restrict__ W2)
{
    const size_t i = (size_t)blockIdx.x * 256 + threadIdx.x;
    reinterpret_cast<float4*>(W2)[i] = reinterpret_cast<const float4*>(Wqkv)[i];
}

// folded bias b2 (3C)
__global__ void b2fold_kernel(const float* __restrict__ bqkv, const float* __restrict__ Wk,
                              const float* __restrict__ bk, const float* __restrict__ Wv,
                              const float* __restrict__ bv, float* __restrict__ b2)
{
    const int i = blockIdx.x * 256 + threadIdx.x;
    if (i < C_) { b2[i] = bqkv[i]; return; }
    const int kv = (i - C_) / C_;            // 0 = K, 1 = V
    const int d = (i - C_) - kv * C_;
    const int h = d >> 6, dd = d & 63;
    const float* W = kv ? Wv : Wk;
    const float* bb = kv ? bv : bk;
    float s = bb[dd];
    for (int e = 0; e < 64; e++)
        s = fmaf(W[dd * 64 + e], bqkv[C_ + kv * C_ + h * 64 + e], s);
    b2[i] = s;
}

// =====================================================================
// q_a[h] = agent_tokens[h] @ Wq^T + bq
// =====================================================================
__global__ __launch_bounds__(256)
void qa_kernel(const float* __restrict__ ag, const float* __restrict__ Wq,
               const float* __restrict__ bq, float* __restrict__ qa)
{
    __shared__ float sA[64 * 65];
    __shared__ float sW[64 * 65];
    const int tid = threadIdx.x;
    const int tx = tid & 15, ty = tid >> 4;
    const int h = blockIdx.x;

    for (int idx = tid; idx < 4096; idx += 256) {
        sA[(idx >> 6) * 65 + (idx & 63)] = ag[h * 4096 + idx];
        sW[(idx >> 6) * 65 + (idx & 63)] = Wq[idx];
    }
    __syncthreads();

    float acc[4][4];
#pragma unroll
    for (int r = 0; r < 4; r++)
#pragma unroll
        for (int c = 0; c < 4; c++) acc[r][c] = bq[tx + 16*c];
#pragma unroll 8
    for (int e = 0; e < 64; e++) {
        float af[4], wf[4];
#pragma unroll
        for (int r = 0; r < 4; r++) af[r] = sA[(ty + 16*r) * 65 + e];
#pragma unroll
        for (int c = 0; c < 4; c++) wf[c] = sW[(tx + 16*c) * 65 + e];
#pragma unroll
        for (int r = 0; r < 4; r++)
#pragma unroll
            for (int c = 0; c < 4; c++) acc[r][c] = fmaf(af[r], wf[c], acc[r][c]);
    }
#pragma unroll
    for (int r = 0; r < 4; r++)
#pragma unroll
        for (int c = 0; c < 4; c++)
            qa[h * 4096 + (ty + 16*r) * 64 + tx + 16*c] = acc[r][c];
}

// b' = Wproj @ bout + bproj
__global__ void bcomb_kernel(const float* __restrict__ Wproj, const float* __restrict__ bout,
                             const float* __restrict__ bproj, float* __restrict__ bcomb)
{
    const int i = blockIdx.x * 256 + threadIdx.x;
    float s = bproj[i];
    for (int k = 0; k < C_; k++) s = fmaf(Wproj[(size_t)i * C_ + k], bout[k], s);
    bcomb[i] = s;
}

// =====================================================================
// Stage 1 (lean): k_a/v_a pre-projected in qkv buffer.
// Per (b,h,chunk) block: stream 64-key tiles, scores vs q_a, online
// softmax, acc += P @ v_a. Split-T partials + combine.
// smem 66.5 KB -> 3 CTAs/SM.
// =====================================================================
constexpr int S1P = 65;
constexpr int S1_SMEM = 4 * 64 * S1P * (int)sizeof(float);   // 66560 B

__global__ __launch_bounds__(256)
void stage1_kernel(const float* __restrict__ qkv, const float* __restrict__ qa,
                   float* __restrict__ pm, float* __restrict__ pl,
                   float* __restrict__ pacc)
{
    extern __shared__ float sm1[];
    float* sQa = sm1;                 // [64][65]  q_a (a,d)
    float* sK  = sQa + 64 * S1P;      // [64][65]  k_a tile (t,d)
    float* sV  = sK  + 64 * S1P;      // [64][65]  v_a tile (t,d)
    float* sP  = sV  + 64 * S1P;      // [64][65]  exp scores (a,t)

    const int tid = threadIdx.x;
    const int tx = tid & 15, ty = tid >> 4;
    const int chunk = blockIdx.x, bh = blockIdx.y;
    const int b = bh >> 4, h = bh & 15;

    for (int idx = tid; idx < 4096; idx += 256)
        sQa[(idx >> 6) * S1P + (idx & 63)] = qa[h * 4096 + idx];

    float m_run[4], l_run[4], acc[4][4];
#pragma unroll
    for (int r = 0; r < 4; r++) {
        m_run[r] = -1e30f; l_run[r] = 0.f;
#pragma unroll
        for (int c = 0; c < 4; c++) acc[r][c] = 0.f;
    }

    const size_t rowbase = (size_t)(b * T_) * C3_;

    for (int kt = 0; kt < CT_ / KT_; kt++) {
        const int t0 = chunk * CT_ + kt * KT_;

        // load k_a and v_a tiles
        for (int idx = tid; idx < 1024; idx += 256) {
            const int row = idx >> 4, c4 = idx & 15;
            const size_t base = rowbase + (size_t)(t0 + row) * C3_ + h * 64 + c4 * 4;
            const float4 kv4 = *reinterpret_cast<const float4*>(qkv + base + C_);
            const float4 vv4 = *reinterpret_cast<const float4*>(qkv + base + 2 * C_);
            float* dk = &sK[row * S1P + c4 * 4];
            float* dv = &sV[row * S1P + c4 * 4];
            dk[0] = kv4.x; dk[1] = kv4.y; dk[2] = kv4.z; dk[3] = kv4.w;
            dv[0] = vv4.x; dv[1] = vv4.y; dv[2] = vv4.z; dv[3] = vv4.w;
        }
        __syncthreads();

        // S = q_a @ k_a^T * scale, online softmax, P -> sP
        {
            float s[4][4];
#pragma unroll
            for (int r = 0; r < 4; r++)
#pragma unroll
                for (int c = 0; c < 4; c++) s[r][c] = 0.f;
#pragma unroll 8
            for (int e = 0; e < 64; e++) {
                float qf[4], kf[4];
#pragma unroll
                for (int r = 0; r < 4; r++) qf[r] = sQa[(ty + 16*r) * S1P + e];
#pragma unroll
                for (int c = 0; c < 4; c++) kf[c] = sK[(tx + 16*c) * S1P + e];
#pragma unroll
                for (int r = 0; r < 4; r++)
#pragma unroll
                    for (int c = 0; c < 4; c++) s[r][c] = fmaf(qf[r], kf[c], s[r][c]);
            }
#pragma unroll
            for (int r = 0; r < 4; r++) {
                float mt = -1e30f;
#pragma unroll
                for (int c = 0; c < 4; c++) { s[r][c] *= SCALE_; mt = fmaxf(mt, s[r][c]); }
#pragma unroll
                for (int ms = 8; ms >= 1; ms >>= 1)
                    mt = fmaxf(mt, __shfl_xor_sync(0xffffffffu, mt, ms));
                const float mn = fmaxf(m_run[r], mt);
                const float corr = __expf(m_run[r] - mn);
                float rs = 0.f;
#pragma unroll
                for (int c = 0; c < 4; c++) {
                    const float p = __expf(s[r][c] - mn);
                    sP[(ty + 16*r) * S1P + tx + 16*c] = p;
                    rs += p;
                }
#pragma unroll
                for (int ms = 8; ms >= 1; ms >>= 1)
                    rs += __shfl_xor_sync(0xffffffffu, rs, ms);
                l_run[r] = l_run[r] * corr + rs;
                m_run[r] = mn;
#pragma unroll
                for (int c = 0; c < 4; c++) acc[r][c] *= corr;
            }
        }
        __syncthreads();

        // acc += P @ v_a
#pragma unroll 8
        for (int t = 0; t < 64; t++) {
            float pf[4], vf[4];
#pragma unroll
            for (int r = 0; r < 4; r++) pf[r] = sP[(ty + 16*r) * S1P + t];
#pragma unroll
            for (int c = 0; c < 4; c++) vf[c] = sV[t * S1P + tx + 16*c];
#pragma unroll
            for (int r = 0; r < 4; r++)
#pragma unroll
                for (int c = 0; c < 4; c++) acc[r][c] = fmaf(pf[r], vf[c], acc[r][c]);
        }
        __syncthreads();   // protect sK/sV/sP before next tile's loads
    }

    const int pi = bh * NCHUNK_ + chunk;
    if (tx == 0) {
#pragma unroll
        for (int r = 0; r < 4; r++) {
            pm[pi * 64 + ty + 16*r] = m_run[r];
            pl[pi * 64 + ty + 16*r] = l_run[r];
        }
    }
#pragma unroll
    for (int r = 0; r < 4; r++)
#pragma unroll
        for (int c = 0; c < 4; c++)
            pacc[(size_t)pi * 4096 + (ty + 16*r) * 64 + tx + 16*c] = acc[r][c];
}

// combine split-T partials -> c1[b,h,a,d]
__global__ __launch_bounds__(256)
void s1combine_kernel(const float* __restrict__ pm, const float* __restrict__ pl,
                      const float* __restrict__ pacc, float* __restrict__ c1)
{
    const int bh = blockIdx.x;
    const int tid = threadIdx.x;
    const int a = tid >> 2, dg = tid & 3;

    float mc[NCHUNK_], lc[NCHUNK_];
    float m = -1e30f;
#pragma unroll
    for (int c = 0; c < NCHUNK_; c++) {
        mc[c] = pm[(bh * NCHUNK_ + c) * 64 + a];
        lc[c] = pl[(bh * NCHUNK_ + c) * 64 + a];
        m = fmaxf(m, mc[c]);
    }
    float l = 0.f, w[NCHUNK_];
#pragma unroll
    for (int c = 0; c < NCHUNK_; c++) { w[c] = __expf(mc[c] - m); l += lc[c] * w[c]; }
    const float inv = 1.f / l;
#pragma unroll
    for (int j = 0; j < 16; j++) {
        const int d = dg * 16 + j;
        float s = 0.f;
#pragma unroll
        for (int c = 0; c < NCHUNK_; c++)
            s += pacc[(size_t)(bh * NCHUNK_ + c) * 4096 + a * 64 + d] * w[c];
        c1[bh * 4096 + a * 64 + d] = s * inv;
    }
}

// =====================================================================
// Stage 2: per (b,h, 128-token tile). Emits s2 + c2.
// =====================================================================
constexpr int S2P = 65;
constexpr int S2_SMEM = (64 + 128 + 128) * S2P * (int)sizeof(float);  // 83200 B

__global__ __launch_bounds__(256)
void stage2_kernel(const float* __restrict__ qkv, const float* __restrict__ c1,
                   float* __restrict__ s2out, float* __restrict__ c2)
{
    extern __shared__ float sm2[];
    float* sC1 = sm2;
    float* sQ  = sC1 + 64 * S2P;
    float* sP  = sQ + 128 * S2P;

    const int tid = threadIdx.x;
    const int tx = tid & 15, ty = tid >> 4;
    const int bh = blockIdx.y;
    const int b = bh >> 4, h = bh & 15;
    const int t0 = blockIdx.x * 128;

    for (int idx = tid; idx < 4096; idx += 256)
        sC1[(idx >> 6) * S2P + (idx & 63)] = c1[bh * 4096 + idx];
    for (int idx = tid; idx < 2048; idx += 256) {
        const int row = idx >> 4, c4 = idx & 15;
        const float4 v = *reinterpret_cast<const float4*>(
            qkv + (size_t)(b * T_ + t0 + row) * C3_ + h * 64 + c4 * 4);
        float* d = &sQ[row * S2P + c4 * 4];
        d[0] = v.x; d[1] = v.y; d[2] = v.z; d[3] = v.w;
    }
    __syncthreads();

    float s[8][4];
#pragma unroll
    for (int r = 0; r < 8; r++)
#pragma unroll
        for (int c = 0; c < 4; c++) s[r][c] = 0.f;
#pragma unroll 8
    for (int d = 0; d < 64; d++) {
        float qf[8], cf[4];
#pragma unroll
        for (int r = 0; r < 8; r++) qf[r] = sQ[(ty + 16*r) * S2P + d];
#pragma unroll
        for (int c = 0; c < 4; c++) cf[c] = sC1[(tx + 16*c) * S2P + d];
#pragma unroll
        for (int r = 0; r < 8; r++)
#pragma unroll
            for (int c = 0; c < 4; c++) s[r][c] = fmaf(qf[r], cf[c], s[r][c]);
    }

#pragma unroll
    for (int r = 0; r < 8; r++) {
        float mt = -1e30f;
#pragma unroll
        for (int c = 0; c < 4; c++) { s[r][c] *= SCALE_; mt = fmaxf(mt, s[r][c]); }
#pragma unroll
        for (int ms = 8; ms >= 1; ms >>= 1)
            mt = fmaxf(mt, __shfl_xor_sync(0xffffffffu, mt, ms));
        float rs = 0.f;
#pragma unroll
        for (int c = 0; c < 4; c++) { s[r][c] = __expf(s[r][c] - mt); rs += s[r][c]; }
#pragma unroll
        for (int ms = 8; ms >= 1; ms >>= 1)
            rs += __shfl_xor_sync(0xffffffffu, rs, ms);
        const float inv = 1.f / rs;
        const int t = t0 + ty + 16*r;
        const size_t so = ((size_t)bh * T_ + t) * 64;
#pragma unroll
        for (int c = 0; c < 4; c++) {
            const float p = s[r][c] * inv;
            sP[(ty + 16*r) * S2P + tx + 16*c] = p;
            s2out[so + tx + 16*c] = p;
        }
    }
    __syncthreads();

    float acc[8][4];
#pragma unroll
    for (int r = 0; r < 8; r++)
#pragma unroll
        for (int c = 0; c < 4; c++) acc[r][c] = 0.f;
#pragma unroll 8
    for (int a = 0; a < 64; a++) {
        float pf[8], cf[4];
#pragma unroll
        for (int r = 0; r < 8; r++) pf[r] = sP[(ty + 16*r) * S2P + a];
#pragma unroll
        for (int c = 0; c < 4; c++) cf[c] = sC1[a * S2P + tx + 16*c];
#pragma unroll
        for (int r = 0; r < 8; r++)
#pragma unroll
            for (int c = 0; c < 4; c++) acc[r][c] = fmaf(pf[r], cf[c], acc[r][c]);
    }
#pragma unroll
    for (int r = 0; r < 8; r++) {
        const int t = t0 + ty + 16*r;
#pragma unroll
        for (int c = 0; c < 4; c++)
            c2[(size_t)(b * T_ + t) * C_ + h * 64 + tx + 16*c] = acc[r][c];
    }
}

// =====================================================================
// launch
// =====================================================================
extern "C" void kernel_launch(void* const* d_in, const int* in_sizes, int n_in,
                              void* d_out, int out_size)
{
    (void)in_sizes; (void)n_in; (void)out_size;
    const float* x     = (const float*)d_in[0];
    const float* Wqkv  = (const float*)d_in[1];
    const float* bqkv  = (const float*)d_in[2];
    const float* Wq    = (const float*)d_in[3];
    const float* bq    = (const float*)d_in[4];
    const float* Wk    = (const float*)d_in[5];
    const float* bk    = (const float*)d_in[6];
    const float* Wv    = (const float*)d_in[7];
    const float* bv    = (const float*)d_in[8];
    const float* ag    = (const float*)d_in[9];
    const float* Wout  = (const float*)d_in[10];
    const float* bout  = (const float*)d_in[11];
    const float* Wproj = (const float*)d_in[12];
    const float* bproj = (const float*)d_in[13];
    float* out = (float*)d_out;

    float *qkv, *w2, *b2, *qa, *pm, *pl, *pacc, *c1, *c2, *wcomb, *bcomb;
    cudaGetSymbolAddress((void**)&qkv,   g_qkv);
    cudaGetSymbolAddress((void**)&w2,    g_w2);
    cudaGetSymbolAddress((void**)&b2,    g_b2);
    cudaGetSymbolAddress((void**)&qa,    g_qa);
    cudaGetSymbolAddress((void**)&pm,    g_pm);
    cudaGetSymbolAddress((void**)&pl,    g_pl);
    cudaGetSymbolAddress((void**)&pacc,  g_pacc);
    cudaGetSymbolAddress((void**)&c1,    g_c1);
    cudaGetSymbolAddress((void**)&c2,    g_c2);
    cudaGetSymbolAddress((void**)&wcomb, g_wcomb);
    cudaGetSymbolAddress((void**)&bcomb, g_bcomb);

    cudaFuncSetAttribute(gemm_tf32_kernel<1>, cudaFuncAttributeMaxDynamicSharedMemorySize, G_SMEM);
    cudaFuncSetAttribute(gemm_tf32_kernel<0>, cudaFuncAttributeMaxDynamicSharedMemorySize, G_SMEM);
    cudaFuncSetAttribute(stage1_kernel, cudaFuncAttributeMaxDynamicSharedMemorySize, S1_SMEM);
    cudaFuncSetAttribute(stage2_kernel, cudaFuncAttributeMaxDynamicSharedMemorySize, S2_SMEM);

    // 0. fold per-head Wk/Wv into Wqkv  (W2, b2)
    copyq_kernel<<<C_ * C_ / (256 * 4), 256>>>(Wqkv, w2);
    wfold_kernel<<<dim3(C_/64, 2*NH_), 256>>>(Wqkv, Wk, Wv, w2);
    b2fold_kernel<<<C3_/256, 256>>>(bqkv, Wk, bk, Wv, bv, b2);
    // 1. qkv = x @ W2^T + b2  ->  [q | k_a | v_a]
    gemm_tf32_kernel<1><<<dim3(C3_/128, BT_/128), 256, G_SMEM>>>(x, w2, b2, qkv, BT_, C3_, C_);
    // 2. q_a (per-head), combined bias, combined weight wcomb = Wproj @ Wout
    qa_kernel<<<NH_, 256>>>(ag, Wq, bq, qa);
    bcomb_kernel<<<C_/256, 256>>>(Wproj, bout, bproj, bcomb);
    gemm_tf32_kernel<0><<<dim3(C_/128, C_/128), 256, G_SMEM>>>(Wproj, Wout, nullptr, wcomb, C_, C_, C_);
    // 3. stage-1 attention (pre-projected k_a/v_a, split-T online softmax)
    stage1_kernel<<<dim3(NCHUNK_, BH_), 256, S1_SMEM>>>(qkv, qa, pm, pl, pacc);
    s1combine_kernel<<<BH_, 256>>>(pm, pl, pacc, c1);
    // 4. stage-2 attention -> s2 (output #2) + c2
    stage2_kernel<<<dim3(T_/128, BH_), 256, S2_SMEM>>>(qkv, c1, out + (size_t)BT_ * C_, c2);
    // 5. y = c2 @ (Wproj@Wout)^T + b'  -> output #1
    gemm_tf32_kernel<1><<<dim3(C_/128, BT_/128), 256, G_SMEM>>>(c2, wcomb, bcomb, out, BT_, C_, C_);
}